// round 1
// baseline (speedup 1.0000x reference)
#include <cuda_runtime.h>

// Problem shape (fixed by the dataset)
#define BB 4096
#define VV 32000

#define CHUNKS   4                    // CTAs per row
#define TPB      256                  // threads per partial CTA
#define ROW_F4   (VV / 4)             // 8000 float4 per row
#define CHUNK_F4 (ROW_F4 / CHUNKS)    // 2000 float4 per chunk
#define PER_TH   ((CHUNK_F4 + TPB - 1) / TPB)  // 8 float4 per thread
#define NPART    (BB * CHUNKS)        // 16384 partials

// Scratch (no allocations allowed) — SoA, 16B-aligned so finalize can float4-load.
__device__ __align__(16) float g_m[NPART];
__device__ __align__(16) float g_s[NPART];
__device__ __align__(16) float g_t[NPART];
__device__ int g_is64;

// ---------------------------------------------------------------------------
// Kernel 0: detect whether `value` is int64 or int32.
// values are in [0, 32000), so if the buffer is int64 (little-endian) every
// odd 32-bit word is 0. If it's int32, odd words are value[1], value[3], ...
// (vanishingly unlikely to all be zero). Reads only the first 4096 words,
// which is in-bounds for both layouts.
// ---------------------------------------------------------------------------
__global__ void detect_dtype_kernel(const int* __restrict__ w) {
    int tid = threadIdx.x;                 // 1024 threads
    int a = w[2 * tid + 1];                // odd words 1..2047
    int b = w[2 * (tid + 1024) + 1];       // odd words 2049..4095
    int any = __syncthreads_or((a | b) != 0);
    if (tid == 0) g_is64 = any ? 0 : 1;
}

// ---------------------------------------------------------------------------
// Kernel 1: per-chunk (m, S, T) partials. One 256-thread CTA per quarter-row.
// Each thread holds 8 float4 (32 floats) in registers: one HBM pass gives
// both the max and the exp-sums. 4 CTAs/SM so load/compute phases of
// different CTAs overlap and HBM stays busy.
// ---------------------------------------------------------------------------
__global__ __launch_bounds__(TPB, 4)
void partial_kernel(const float* __restrict__ logits) {
    const int bid   = blockIdx.x;
    const int row   = bid >> 2;       // CHUNKS == 4
    const int chunk = bid & 3;
    const int tid   = threadIdx.x;

    const float4* __restrict__ p4 =
        reinterpret_cast<const float4*>(logits) +
        (size_t)row * ROW_F4 + (size_t)chunk * CHUNK_F4;

    // ---- load slice into registers, track local max ----
    float4 v[PER_TH];
    float mloc = -3.0e38f;
#pragma unroll
    for (int k = 0; k < PER_TH; k++) {
        int idx = k * TPB + tid;
        if (idx < CHUNK_F4) {
            v[k] = p4[idx];
        } else {
            v[k] = make_float4(-1e30f, -1e30f, -1e30f, -1e30f); // exp -> 0, e*t -> -0
        }
        mloc = fmaxf(mloc, fmaxf(fmaxf(v[k].x, v[k].y), fmaxf(v[k].z, v[k].w)));
    }

    // ---- block-reduce max ----
    const unsigned FULL = 0xffffffffu;
#pragma unroll
    for (int o = 16; o; o >>= 1)
        mloc = fmaxf(mloc, __shfl_xor_sync(FULL, mloc, o));

    __shared__ float smax[TPB / 32];
    __shared__ float ssum[TPB / 32];
    __shared__ float stsm[TPB / 32];
    const int wid  = tid >> 5;
    const int lane = tid & 31;
    if (lane == 0) smax[wid] = mloc;
    __syncthreads();

    float bm = smax[0];
#pragma unroll
    for (int w = 1; w < TPB / 32; w++) bm = fmaxf(bm, smax[w]);

    // ---- exp pass over registers: S = sum e^(x-m), T = sum e^(x-m)*(x-m) ----
    float S = 0.0f, T = 0.0f;
#pragma unroll
    for (int k = 0; k < PER_TH; k++) {
        float x0 = v[k].x, x1 = v[k].y, x2 = v[k].z, x3 = v[k].w;
        float t0 = x0 - bm, t1 = x1 - bm, t2 = x2 - bm, t3 = x3 - bm;
        float e0 = __expf(t0), e1 = __expf(t1), e2 = __expf(t2), e3 = __expf(t3);
        S += e0; T = fmaf(e0, t0, T);
        S += e1; T = fmaf(e1, t1, T);
        S += e2; T = fmaf(e2, t2, T);
        S += e3; T = fmaf(e3, t3, T);
    }

    // ---- block-reduce (S, T) ----
#pragma unroll
    for (int o = 16; o; o >>= 1) {
        S += __shfl_xor_sync(FULL, S, o);
        T += __shfl_xor_sync(FULL, T, o);
    }
    if (lane == 0) { ssum[wid] = S; stsm[wid] = T; }
    __syncthreads();

    if (tid == 0) {
        float Sb = 0.0f, Tb = 0.0f;
#pragma unroll
        for (int w = 0; w < TPB / 32; w++) { Sb += ssum[w]; Tb += stsm[w]; }
        g_m[bid] = bm;
        g_s[bid] = Sb;
        g_t[bid] = Tb;
    }
}

// ---------------------------------------------------------------------------
// Kernel 2: merge 4 partials per row, gather logits[r, value[r]], emit
// [pdf, log_prob, negative-entropy] laid out as [3, B].
// Rebase identity: with d = m_c - m (<= 0):
//   sum e^(x-m)        = e^d * S_c
//   sum e^(x-m)(x-m)   = e^d * (T_c + d * S_c)
// ---------------------------------------------------------------------------
__global__ void finalize_kernel(const float* __restrict__ logits,
                                const void* __restrict__ value,
                                float* __restrict__ out) {
    int r = blockIdx.x * blockDim.x + threadIdx.x;
    if (r >= BB) return;

    float4 mc = reinterpret_cast<const float4*>(g_m)[r];
    float4 sc = reinterpret_cast<const float4*>(g_s)[r];
    float4 tc = reinterpret_cast<const float4*>(g_t)[r];

    float m = fmaxf(fmaxf(mc.x, mc.y), fmaxf(mc.z, mc.w));

    float mm[4] = {mc.x, mc.y, mc.z, mc.w};
    float ss[4] = {sc.x, sc.y, sc.z, sc.w};
    float tt[4] = {tc.x, tc.y, tc.z, tc.w};

    float S = 0.0f, T = 0.0f;
#pragma unroll
    for (int c = 0; c < 4; c++) {
        float d = mm[c] - m;
        float e = __expf(d);
        S += e * ss[c];
        T += e * (tt[c] + d * ss[c]);
    }

    long long vi;
    if (g_is64) vi = reinterpret_cast<const long long*>(value)[r];
    else        vi = (long long)reinterpret_cast<const int*>(value)[r];

    float xv   = logits[(size_t)r * VV + (size_t)vi];
    float tv   = xv - m;
    float logS = logf(S);

    out[r]          = __expf(tv) / S;   // pdf
    out[BB + r]     = tv - logS;        // log_prob
    out[2 * BB + r] = T / S - logS;     // sum p*log p (reference's sign)
}

extern "C" void kernel_launch(void* const* d_in, const int* in_sizes, int n_in,
                              void* d_out, int out_size) {
    const float* logits = (const float*)d_in[0];
    const void*  value  = d_in[1];
    float*       out    = (float*)d_out;

    detect_dtype_kernel<<<1, 1024>>>((const int*)value);
    partial_kernel<<<NPART, TPB>>>(logits);
    finalize_kernel<<<(BB + 127) / 128, 128>>>(logits, value, out);
}